// round 7
// baseline (speedup 1.0000x reference)
#include <cuda_runtime.h>
#include <cstdint>
#include <cstddef>

#define T_STEPS 1024
#define BATCH   64
#define DDIM    128
#define HDIM    512
#define ALPHA   0.1f

#define CLUSTER 8
#define BPC     4
#define NTHR    512

#define ABUF_FLOATS  2560                 // [k(640)][b(4)] ; k<512 fr, k>=512 x
#define SA_FLOATS    (2 * ABUF_FLOATS)    // ping-pong
#define MBAR_OFF     SA_FLOATS            // float idx; 8B aligned
#define SMEM_BYTES   ((MBAR_OFF + 8) * 4)

#define TX_BYTES 7168                     // 7 peers x 1KB (own slice is local STS)

// ---- packed fp32x2 helpers ----
__device__ __forceinline__ unsigned long long fma2(unsigned long long a,
                                                   unsigned long long b,
                                                   unsigned long long c) {
    unsigned long long d;
    asm("fma.rn.f32x2 %0, %1, %2, %3;" : "=l"(d) : "l"(a), "l"(b), "l"(c));
    return d;
}
__device__ __forceinline__ unsigned long long splat2(float x) {
    unsigned long long d;
    asm("mov.b64 %0, {%1, %1};" : "=l"(d) : "f"(x));
    return d;
}
__device__ __forceinline__ unsigned long long pack2(float lo, float hi) {
    unsigned long long d;
    asm("mov.b64 %0, {%1, %2};" : "=l"(d) : "f"(lo), "f"(hi));
    return d;
}
__device__ __forceinline__ float lo32(unsigned long long v) {
    return __uint_as_float((unsigned)(v & 0xFFFFFFFFull));
}
__device__ __forceinline__ float hi32(unsigned long long v) {
    return __uint_as_float((unsigned)(v >> 32));
}

// ---- cluster / mbarrier helpers ----
__device__ __forceinline__ unsigned mapa_u32(unsigned addr, unsigned rank) {
    unsigned d;
    asm("mapa.shared::cluster.u32 %0, %1, %2;" : "=r"(d) : "r"(addr), "r"(rank));
    return d;
}
__device__ __forceinline__ void mbar_init(unsigned addr, unsigned cnt) {
    asm volatile("mbarrier.init.shared.b64 [%0], %1;" :: "r"(addr), "r"(cnt) : "memory");
}
__device__ __forceinline__ void mbar_arrive_expect_tx(unsigned addr, unsigned bytes) {
    asm volatile("mbarrier.arrive.expect_tx.shared.b64 _, [%0], %1;"
                 :: "r"(addr), "r"(bytes) : "memory");
}
__device__ __forceinline__ void mbar_wait_parity(unsigned addr, unsigned parity) {
    unsigned done;
    asm volatile(
        "{\n\t.reg .pred p;\n\t"
        "mbarrier.try_wait.parity.acquire.cta.shared::cta.b64 p, [%1], %2;\n\t"
        "selp.b32 %0, 1, 0, p;\n\t}"
        : "=r"(done) : "r"(addr), "r"(parity) : "memory");
    if (!done) {
        asm volatile(
            "{\n\t.reg .pred P1;\n\t"
            "WAIT_LOOP_%=:\n\t"
            "mbarrier.try_wait.parity.acquire.cta.shared::cta.b64 P1, [%0], %1, 0x989680;\n\t"
            "@P1 bra.uni WAIT_DONE_%=;\n\t"
            "bra.uni WAIT_LOOP_%=;\n\t"
            "WAIT_DONE_%=:\n\t}"
            :: "r"(addr), "r"(parity) : "memory");
    }
}
__device__ __forceinline__ void bulk_dsmem(unsigned dst_cluster, unsigned src_cta,
                                           unsigned bytes, unsigned mbar_cluster) {
    asm volatile(
        "cp.async.bulk.shared::cluster.shared::cta.mbarrier::complete_tx::bytes "
        "[%0], [%1], %2, [%3];"
        :: "r"(dst_cluster), "r"(src_cta), "r"(bytes), "r"(mbar_cluster) : "memory");
}
__device__ __forceinline__ void fence_proxy_async_cta() {
    asm volatile("fence.proxy.async.shared::cta;" ::: "memory");
}
__device__ __forceinline__ void cluster_sync_() {
    asm volatile("barrier.cluster.arrive.aligned;" ::: "memory");
    asm volatile("barrier.cluster.wait.aligned;" ::: "memory");
}

__global__ void __launch_bounds__(NTHR, 1)
rnn_kernel(const float* __restrict__ input, const float* __restrict__ Win,
           const float* __restrict__ bin,   const float* __restrict__ Whid,
           const float* __restrict__ bhid,  float* __restrict__ out)
{
    extern __shared__ float sA[];   // [2][640][4] | mbar[2]

    const int tid  = threadIdx.x;
    const int lane = tid & 31;
    const int w    = tid >> 5;
    const int bx   = blockIdx.x;
    const int rank = bx & (CLUSTER - 1);
    const int cl   = bx >> 3;
    const int b0   = cl * BPC;
    const int g0   = rank * 64;
    const int gbase = g0 + w * 4;

    // Rotated chunk map: weight slot j <-> k-chunk (j + 2*rank + 2) & 15.
    // Own fr chunks (k-chunks 2*rank, 2*rank+1) land at STATIC slots 14, 15.
    const int R = (((rank * 2 + 2) & 15) * 32);   // k offset of slot 0
    #define FRIDX(J) (((((J) * 32) + R) & 511) + lane)

    // lane's output after the butterfly (verified mapping):
    const int vidx = ((lane >> 4) & 1) * 8 + ((lane >> 3) & 1) * 4
                   + ((lane >> 2) & 1) * 2 + ((lane >> 1) & 1);
    const int gl = vidx >> 2;
    const int bb = vidx & 3;
    const int hmine = gbase + gl;

    // ---- W into registers (pre-scaled by ALPHA), slot-rotated, static idx ----
    unsigned long long wA[20], wB[20];
    #pragma unroll
    for (int j = 0; j < 16; ++j) {
        int k = FRIDX(j);
        wA[j] = pack2(ALPHA * Whid[(gbase + 0) * HDIM + k],
                      ALPHA * Whid[(gbase + 1) * HDIM + k]);
        wB[j] = pack2(ALPHA * Whid[(gbase + 2) * HDIM + k],
                      ALPHA * Whid[(gbase + 3) * HDIM + k]);
    }
    #pragma unroll
    for (int j = 16; j < 20; ++j) {
        int k = (j - 16) * 32 + lane;
        wA[j] = pack2(ALPHA * Win[(gbase + 0) * DDIM + k],
                      ALPHA * Win[(gbase + 1) * DDIM + k]);
        wB[j] = pack2(ALPHA * Win[(gbase + 2) * DDIM + k],
                      ALPHA * Win[(gbase + 3) * DDIM + k]);
    }
    const float breg = ALPHA * (bhid[hmine] + bin[hmine]);
    float vreg = 0.0f;

    const unsigned smemBase = (unsigned)__cvta_generic_to_shared(sA);
    const unsigned mbarBase = smemBase + MBAR_OFF * 4;

    // ---- init: buffer0 fr = 0 ; x = input[t=0]; arm both mbars ----
    {
        float4 z = {0.f, 0.f, 0.f, 0.f};
        ((float4*)sA)[tid] = z;
        int d = w * 8 + (lane >> 2);
        int b = lane & 3;
        sA[(HDIM + d) * 4 + b] = input[(size_t)(b0 + b) * DDIM + d];
    }
    if (tid == 0) {
        mbar_init(mbarBase + 0, 1);
        mbar_init(mbarBase + 8, 1);
        mbar_arrive_expect_tx(mbarBase + 0, TX_BYTES);
        mbar_arrive_expect_tx(mbarBase + 8, TX_BYTES);
    }
    __syncthreads();
    cluster_sync_();   // mbars live before any peer bulk-copy can land

    const int xd = w * 8 + (lane >> 2);
    const int xb = lane & 3;

    #define GEMM_STEP(KIDX, KK)                                                \
        {                                                                      \
            float4 a4 = *(const float4*)&aBuf[(KIDX) * 4];                     \
            unsigned long long s0 = splat2(a4.x), s1 = splat2(a4.y);           \
            unsigned long long s2 = splat2(a4.z), s3 = splat2(a4.w);           \
            acc[0] = fma2(wA[KK], s0, acc[0]); acc[1] = fma2(wB[KK], s0, acc[1]);\
            acc[2] = fma2(wA[KK], s1, acc[2]); acc[3] = fma2(wB[KK], s1, acc[3]);\
            acc[4] = fma2(wA[KK], s2, acc[4]); acc[5] = fma2(wB[KK], s2, acc[5]);\
            acc[6] = fma2(wA[KK], s3, acc[6]); acc[7] = fma2(wB[KK], s3, acc[7]);\
        }

    // ---- prologue: own-fr slots (zero data) + x slots, on buffer 0 ----
    unsigned long long acc[8];
    #pragma unroll
    for (int i = 0; i < 8; ++i) acc[i] = 0ull;
    {
        const float* aBuf = sA;
        GEMM_STEP(FRIDX(14), 14)
        GEMM_STEP(FRIDX(15), 15)
        #pragma unroll
        for (int j = 16; j < 20; ++j)
            GEMM_STEP(HDIM + (j - 16) * 32 + lane, j)
    }

    int ph0 = 0, ph1 = 0;
    int cur = 0;
    for (int t = 0; t < T_STEPS; ++t) {
        // ---- wait for 7 peers' fr(t); re-arm for t+2 ----
        if (t > 0) {
            unsigned mb = mbarBase + (unsigned)(cur * 8);
            unsigned par = (unsigned)(cur ? ph1 : ph0);
            mbar_wait_parity(mb, par);
            if (cur) ph1 ^= 1; else ph0 ^= 1;
            if (tid == 0) mbar_arrive_expect_tx(mb, TX_BYTES);
        }

        // prefetch x(t+1) — hidden under main GEMM
        float xv = 0.f;
        if (t + 1 < T_STEPS)
            xv = input[((size_t)(t + 1) * BATCH + b0 + xb) * DDIM + xd];

        const float* aBuf = sA + cur * ABUF_FLOATS;

        // ---- main GEMM: 14 peer chunks (slots 0..13), static weight idx ----
        #pragma unroll
        for (int j = 0; j < 14; ++j)
            GEMM_STEP(FRIDX(j), j)

        // ---- unpack + warp butterfly (16 outputs over 32 lanes) ----
        float v[16];
        #pragma unroll
        for (int b = 0; b < 4; ++b) {
            v[0 * 4 + b] = lo32(acc[2 * b]);
            v[1 * 4 + b] = hi32(acc[2 * b]);
            v[2 * 4 + b] = lo32(acc[2 * b + 1]);
            v[3 * 4 + b] = hi32(acc[2 * b + 1]);
        }
        #pragma unroll
        for (int s = 16, cnt = 16; s >= 2; s >>= 1, cnt >>= 1) {
            const bool up = (lane & s) != 0;
            const int half = cnt >> 1;
            #pragma unroll
            for (int i = 0; i < 8; ++i) {
                if (i >= half) break;
                float keep = up ? v[i + half] : v[i];
                float send = up ? v[i] : v[i + half];
                float got  = __shfl_xor_sync(0xFFFFFFFFu, send, s);
                v[i] = keep + got;
            }
        }
        v[0] += __shfl_xor_sync(0xFFFFFFFFu, v[0], 1);

        // ---- leaky update + relu ----
        vreg = (1.0f - ALPHA) * vreg + (v[0] + breg);
        float fr = fmaxf(vreg, 0.f);
        if ((lane & 1) == 0)
            out[((size_t)t * BATCH + b0 + bb) * HDIM + hmine] = fr;

        if (t + 1 < T_STEPS) {
            const int nxt = cur ^ 1;
            float* nbuf = sA + nxt * ABUF_FLOATS;

            // own fr slice straight into next buffer (also the bulk source)
            float frb1 = __shfl_xor_sync(0xFFFFFFFFu, fr, 2);
            unsigned long long p01 = pack2(fr, frb1);
            unsigned long long p23 = __shfl_xor_sync(0xFFFFFFFFu, p01, 4);
            if ((lane & 7) == 0)
                *(float4*)&nbuf[hmine * 4] =
                    make_float4(lo32(p01), hi32(p01), lo32(p23), hi32(p23));
            // stage x(t+1)
            nbuf[(HDIM + xd) * 4 + xb] = xv;

            __syncthreads();   // own slice + x visible CTA-wide

            // 7 threads push the 1KB own-slice to the 7 peers in parallel
            if (tid < 7) {
                fence_proxy_async_cta();
                unsigned c = (unsigned)tid + ((tid >= rank) ? 1u : 0u);
                unsigned src  = smemBase + (unsigned)((nxt * ABUF_FLOATS + g0 * 4) * 4);
                unsigned dOff = src;                      // same offset in peer
                unsigned mOff = mbarBase + (unsigned)(nxt * 8);
                bulk_dsmem(mapa_u32(dOff, c), src, 1024, mapa_u32(mOff, c));
            }

            // ---- pre-wait GEMM for t+1: own fr (slots 14,15) + x (16..19) ----
            #pragma unroll
            for (int i = 0; i < 8; ++i) acc[i] = 0ull;
            {
                const float* aBuf = nbuf;
                GEMM_STEP(FRIDX(14), 14)
                GEMM_STEP(FRIDX(15), 15)
                #pragma unroll
                for (int j = 16; j < 20; ++j)
                    GEMM_STEP(HDIM + (j - 16) * 32 + lane, j)
            }
        }
        cur ^= 1;
    }
}

extern "C" void kernel_launch(void* const* d_in, const int* in_sizes, int n_in,
                              void* d_out, int out_size)
{
    const float* input = (const float*)d_in[0];
    const float* Win   = (const float*)d_in[1];
    const float* bin   = (const float*)d_in[2];
    const float* Whid  = (const float*)d_in[3];
    const float* bhid  = (const float*)d_in[4];
    float* out = (float*)d_out;

    cudaFuncSetAttribute(rnn_kernel,
                         cudaFuncAttributeMaxDynamicSharedMemorySize, SMEM_BYTES);

    cudaLaunchConfig_t cfg = {};
    cfg.gridDim  = dim3(16 * CLUSTER, 1, 1);
    cfg.blockDim = dim3(NTHR, 1, 1);
    cfg.dynamicSmemBytes = SMEM_BYTES;
    cfg.stream = 0;

    cudaLaunchAttribute attr[1];
    attr[0].id = cudaLaunchAttributeClusterDimension;
    attr[0].val.clusterDim.x = CLUSTER;
    attr[0].val.clusterDim.y = 1;
    attr[0].val.clusterDim.z = 1;
    cfg.attrs = attr;
    cfg.numAttrs = 1;

    cudaLaunchKernelEx(&cfg, rnn_kernel, input, Win, bin, Whid, bhid, out);
}